// round 3
// baseline (speedup 1.0000x reference)
#include <cuda_runtime.h>
#include <cuda_bf16.h>

// Problem constants (fixed by the reference: B=512, V=32768, C=16)
#define BB   512
#define VV   32768
#define CC   16
#define TPB  256
#define SPLIT 8
#define BPS  (BB / SPLIT)      // 64 samples per split
#define VBLOCKS (VV / TPB)     // 128 v-tiles

// Deterministic scratch: per-split partial sums [SPLIT][C][V] (16 MB) + counts.
__device__ float g_partial[(size_t)SPLIT * CC * VV];
__device__ int   g_counts[CC];
__device__ int   g_init[CC];

// ---------------------------------------------------------------------------
// Kernel (launched 2nd): per-class counts + decode `initialized` (dtype sniff)
// ---------------------------------------------------------------------------
__global__ void prep_kernel(const int* __restrict__ labels,
                            const unsigned char* __restrict__ initp) {
    __shared__ int cnt[CC];
    __shared__ int mode;  // 0=uint8, 1=int32, 2=float32
    if (threadIdx.x == 0) {
        bool i32like = true, f32like = true, anyNZ = false;
        for (int i = 0; i < 16; ++i) {
            if ((i & 3) != 0 && initp[i] != 0) i32like = false;
            if (initp[i] != 0) anyNZ = true;
        }
        const float* fp = (const float*)initp;
        for (int c = 0; c < 4; ++c) {
            float f = fp[c];
            if (!(f == 0.0f || f == 1.0f)) f32like = false;
        }
        if (!anyNZ)        mode = 0;
        else if (f32like)  mode = 2;
        else if (i32like)  mode = 1;
        else               mode = 0;
    }
    if (threadIdx.x < CC) cnt[threadIdx.x] = 0;
    __syncthreads();
    if (threadIdx.x < CC) {
        int c = threadIdx.x, v;
        if (mode == 2)      v = (((const float*)initp)[c] != 0.0f);
        else if (mode == 1) v = (((const int*)initp)[c] != 0);
        else                v = (initp[c] != 0);
        g_init[c] = v;
    }
    for (int b = threadIdx.x; b < BB; b += blockDim.x)
        atomicAdd(&cnt[labels[b]], 1);
    __syncthreads();
    if (threadIdx.x < CC) g_counts[threadIdx.x] = cnt[threadIdx.x];
}

// ---------------------------------------------------------------------------
// Kernel (launched 1st -> lands in ncu capture slot): gather + |sv*w| +
// segment-sum into per-split partials. Grid (VBLOCKS, SPLIT); each thread
// owns one v column for 64 b's, accumulating in smem[class][tid]
// (same class across warp -> broadcast LDS + conflict-free STS).
// ---------------------------------------------------------------------------
__global__ __launch_bounds__(TPB) void accum_kernel(
    const float* __restrict__ sv,
    const float* __restrict__ W,
    const int*   __restrict__ labels)
{
    __shared__ float acc[CC][TPB];
    __shared__ int   slab[BPS];

    const int tid   = threadIdx.x;
    const int v     = blockIdx.x * TPB + tid;
    const int split = blockIdx.y;
    const int b0    = split * BPS;

    if (tid < BPS) slab[tid] = labels[b0 + tid];
#pragma unroll
    for (int c = 0; c < CC; ++c) acc[c][tid] = 0.0f;
    __syncthreads();

    const float* svp = sv + (size_t)b0 * VV + v;
    const float* Wp  = W  + ((size_t)b0 * VV + v) * CC;

    // 8 b's per batch: 16 independent global loads in flight per thread.
#pragma unroll 1
    for (int bb = 0; bb < BPS; bb += 8) {
        int   l[8];
        float s[8];
        float w[8];
#pragma unroll
        for (int k = 0; k < 8; ++k) l[k] = slab[bb + k];
#pragma unroll
        for (int k = 0; k < 8; ++k)
            s[k] = __ldcs(svp + (size_t)(bb + k) * VV);
#pragma unroll
        for (int k = 0; k < 8; ++k)
            w[k] = __ldcs(Wp + (size_t)(bb + k) * VV * CC + l[k]);
#pragma unroll
        for (int k = 0; k < 8; ++k)
            acc[l[k]][tid] += fabsf(s[k] * w[k]);
    }

    // Coalesced partial write (fully written -> no zeroing needed)
    float* outp = g_partial + ((size_t)split * CC) * VV + v;
#pragma unroll
    for (int c = 0; c < CC; ++c)
        outp[(size_t)c * VV] = acc[c][tid];
}

// ---------------------------------------------------------------------------
// Kernel (launched 3rd): reduce splits, mean, EMA / copy / no-op. float4.
// ---------------------------------------------------------------------------
__global__ __launch_bounds__(256) void finalize_kernel(
    const float* __restrict__ centroids,
    float*       __restrict__ out)
{
    const int idx4 = blockIdx.x * blockDim.x + threadIdx.x;   // over C*V/4
    const int idx  = idx4 * 4;
    const int c    = idx >> 15;          // /V
    const int v    = idx & (VV - 1);

    float4 s = make_float4(0.f, 0.f, 0.f, 0.f);
#pragma unroll
    for (int p = 0; p < SPLIT; ++p) {
        const float4 t = *(const float4*)&g_partial[((size_t)p * CC + c) * VV + v];
        s.x += t.x; s.y += t.y; s.z += t.z; s.w += t.w;
    }

    const int   cnt  = g_counts[c];
    const float inv  = 1.0f / fmaxf((float)cnt, 1.0f);
    const int   ini  = g_init[c];
    const float ALPHA = (float)(2.0 / 1001.0);  // 1 - MOMENTUM

    const float4 ct = *(const float4*)&centroids[idx];
    float4 r;
    {
        float m, u;
        m = s.x * inv; u = ini ? (ct.x + ALPHA * (m - ct.x)) : m; r.x = cnt > 0 ? u : ct.x;
        m = s.y * inv; u = ini ? (ct.y + ALPHA * (m - ct.y)) : m; r.y = cnt > 0 ? u : ct.y;
        m = s.z * inv; u = ini ? (ct.z + ALPHA * (m - ct.z)) : m; r.z = cnt > 0 ? u : ct.z;
        m = s.w * inv; u = ini ? (ct.w + ALPHA * (m - ct.w)) : m; r.w = cnt > 0 ? u : ct.w;
    }
    *(float4*)&out[idx] = r;
}

// ---------------------------------------------------------------------------
// Launch. Inputs bound by UNIQUE element count (robust to metadata order):
//   sparse_vector f32 [B,V]     -> 16,777,216
//   W_eff         f32 [B,V,C]   -> 268,435,456
//   labels        i32 [B]       -> 512
//   centroids     f32 [C,V]     -> 524,288
//   initialized   bool[C]       -> 16
// Launch order accum -> prep -> finalize keeps deps valid AND places accum
// in the ncu capture slot (slot == 1 mod 3 observed last round).
// ---------------------------------------------------------------------------
extern "C" void kernel_launch(void* const* d_in, const int* in_sizes, int n_in,
                              void* d_out, int out_size)
{
    const float*         sv   = nullptr;
    const float*         W    = nullptr;
    const int*           lab  = nullptr;
    const float*         cent = nullptr;
    const unsigned char* init = nullptr;

    for (int i = 0; i < n_in; ++i) {
        long n = (long)in_sizes[i];
        if      (n == (long)BB * VV)       sv   = (const float*)d_in[i];
        else if (n == (long)BB * VV * CC)  W    = (const float*)d_in[i];
        else if (n == (long)BB)            lab  = (const int*)d_in[i];
        else if (n == (long)CC * VV)       cent = (const float*)d_in[i];
        else if (n == (long)CC)            init = (const unsigned char*)d_in[i];
    }
    if (!sv)   sv   = (const float*)d_in[0];
    if (!W)    W    = (const float*)d_in[1];
    if (!lab)  lab  = (const int*)d_in[2];
    if (!cent) cent = (const float*)d_in[3];
    if (!init) init = (const unsigned char*)d_in[4];

    float* out = (float*)d_out;

    accum_kernel<<<dim3(VBLOCKS, SPLIT), TPB>>>(sv, W, lab);
    prep_kernel<<<1, 256>>>(lab, init);
    finalize_kernel<<<(CC * VV / 4) / 256, 256>>>(cent, out);
}

// round 4
// speedup vs baseline: 1.0205x; 1.0205x over previous
#include <cuda_runtime.h>
#include <cuda_bf16.h>

// Problem constants (fixed by the reference: B=512, V=32768, C=16)
#define BB   512
#define VV   32768
#define CC   16
#define TPB  256
#define SPLIT 8
#define BPS  (BB / SPLIT)      // 64 samples per split
#define VBLOCKS (VV / TPB)     // 128 v-tiles

// Deterministic scratch: per-split partial sums [SPLIT][C][V] (16 MB).
__device__ float g_partial[(size_t)SPLIT * CC * VV];

// ---------------------------------------------------------------------------
// Kernel 1 (first launch -> ncu capture slot): gather + |sv*w| + segment-sum
// into per-split partials. Grid (VBLOCKS, SPLIT); each thread owns one v
// column for 64 b's, accumulating in smem[class][tid] (same class across
// warp -> broadcast LDS + conflict-free STS). DRAM-bound at ~87% of peak:
// W_eff gather is 1 useful float per 64B burst -> ~1.07 GB mandatory traffic.
// ---------------------------------------------------------------------------
__global__ __launch_bounds__(TPB) void accum_kernel(
    const float* __restrict__ sv,
    const float* __restrict__ W,
    const int*   __restrict__ labels)
{
    __shared__ float acc[CC][TPB];
    __shared__ int   slab[BPS];

    const int tid   = threadIdx.x;
    const int v     = blockIdx.x * TPB + tid;
    const int split = blockIdx.y;
    const int b0    = split * BPS;

    if (tid < BPS) slab[tid] = labels[b0 + tid];
#pragma unroll
    for (int c = 0; c < CC; ++c) acc[c][tid] = 0.0f;
    __syncthreads();

    const float* svp = sv + (size_t)b0 * VV + v;
    const float* Wp  = W  + ((size_t)b0 * VV + v) * CC;

    // 8 b's per batch: 16 independent global loads in flight per thread.
#pragma unroll 1
    for (int bb = 0; bb < BPS; bb += 8) {
        int   l[8];
        float s[8];
        float w[8];
#pragma unroll
        for (int k = 0; k < 8; ++k) l[k] = slab[bb + k];
#pragma unroll
        for (int k = 0; k < 8; ++k)
            s[k] = __ldcs(svp + (size_t)(bb + k) * VV);
#pragma unroll
        for (int k = 0; k < 8; ++k)
            w[k] = __ldcs(Wp + (size_t)(bb + k) * VV * CC + l[k]);
#pragma unroll
        for (int k = 0; k < 8; ++k)
            acc[l[k]][tid] += fabsf(s[k] * w[k]);
    }

    // Coalesced partial write (fully written -> no zeroing needed).
    // Default store policy keeps these L2-resident for the finalize pass.
    float* outp = g_partial + ((size_t)split * CC) * VV + v;
#pragma unroll
    for (int c = 0; c < CC; ++c)
        outp[(size_t)c * VV] = acc[c][tid];
}

// ---------------------------------------------------------------------------
// Kernel 2: fused count + init-decode + split-reduce + mean + EMA. float4.
// 512 blocks; each block's 1024 contiguous outputs lie in exactly one class c,
// so each block recomputes cnt[c] from the 2KB labels array (L2 broadcast,
// fully parallel -- replaces the old serial-latency prep kernel) and thread 0
// sniffs the `initialized` dtype with two vector loads.
// ---------------------------------------------------------------------------
__global__ __launch_bounds__(256) void finalize_kernel(
    const float*         __restrict__ centroids,
    const int*           __restrict__ labels,
    const unsigned char* __restrict__ initp,
    float*               __restrict__ out)
{
    const int idx4 = blockIdx.x * blockDim.x + threadIdx.x;   // over C*V/4
    const int idx  = idx4 * 4;
    const int c    = idx >> 15;          // /V  (constant within a block)
    const int v    = idx & (VV - 1);

    __shared__ int s_cnt;
    __shared__ int s_ini;
    if (threadIdx.x == 0) s_cnt = 0;
    __syncthreads();

    // Per-block count of labels == c (2 loads per thread, no serial chains).
    int my = 0;
#pragma unroll
    for (int b = threadIdx.x; b < BB; b += 256)
        my += (labels[b] == c);
    if (my) atomicAdd(&s_cnt, my);

    // Thread 0: decode initialized[c] with dtype sniff (vector loads).
    if (threadIdx.x == 0) {
        const int4  i4 = *(const int4*)initp;          // first 16 bytes
        const unsigned char* bp = (const unsigned char*)&i4;
        bool i32like = true, f32like = true, anyNZ = false;
        for (int i = 0; i < 16; ++i) {
            if ((i & 3) != 0 && bp[i] != 0) i32like = false;
            if (bp[i] != 0) anyNZ = true;
        }
        const float* fp = (const float*)&i4;
        for (int k = 0; k < 4; ++k)
            if (!(fp[k] == 0.0f || fp[k] == 1.0f)) f32like = false;

        int ini;
        if (!anyNZ)       ini = 0;                         // all-zero: representations agree
        else if (f32like) ini = (((const float*)initp)[c] != 0.0f);
        else if (i32like) ini = (((const int*)initp)[c] != 0);
        else              ini = (initp[c] != 0);
        s_ini = ini;
    }
    __syncthreads();

    const int cnt = s_cnt;
    const int ini = s_ini;

    // Deterministic split reduction (fixed order p = 0..7).
    float4 s = make_float4(0.f, 0.f, 0.f, 0.f);
#pragma unroll
    for (int p = 0; p < SPLIT; ++p) {
        const float4 t = *(const float4*)&g_partial[((size_t)p * CC + c) * VV + v];
        s.x += t.x; s.y += t.y; s.z += t.z; s.w += t.w;
    }

    const float inv   = 1.0f / fmaxf((float)cnt, 1.0f);
    const float ALPHA = (float)(2.0 / 1001.0);  // 1 - MOMENTUM

    const float4 ct = *(const float4*)&centroids[idx];
    float4 r;
    {
        float m, u;
        m = s.x * inv; u = ini ? (ct.x + ALPHA * (m - ct.x)) : m; r.x = cnt > 0 ? u : ct.x;
        m = s.y * inv; u = ini ? (ct.y + ALPHA * (m - ct.y)) : m; r.y = cnt > 0 ? u : ct.y;
        m = s.z * inv; u = ini ? (ct.z + ALPHA * (m - ct.z)) : m; r.z = cnt > 0 ? u : ct.z;
        m = s.w * inv; u = ini ? (ct.w + ALPHA * (m - ct.w)) : m; r.w = cnt > 0 ? u : ct.w;
    }
    *(float4*)&out[idx] = r;
}

// ---------------------------------------------------------------------------
// Launch. Inputs bound by UNIQUE element count (robust to metadata order):
//   sparse_vector f32 [B,V]     -> 16,777,216
//   W_eff         f32 [B,V,C]   -> 268,435,456
//   labels        i32 [B]       -> 512
//   centroids     f32 [C,V]     -> 524,288
//   initialized   bool[C]       -> 16
// ---------------------------------------------------------------------------
extern "C" void kernel_launch(void* const* d_in, const int* in_sizes, int n_in,
                              void* d_out, int out_size)
{
    const float*         sv   = nullptr;
    const float*         W    = nullptr;
    const int*           lab  = nullptr;
    const float*         cent = nullptr;
    const unsigned char* init = nullptr;

    for (int i = 0; i < n_in; ++i) {
        long n = (long)in_sizes[i];
        if      (n == (long)BB * VV)       sv   = (const float*)d_in[i];
        else if (n == (long)BB * VV * CC)  W    = (const float*)d_in[i];
        else if (n == (long)BB)            lab  = (const int*)d_in[i];
        else if (n == (long)CC * VV)       cent = (const float*)d_in[i];
        else if (n == (long)CC)            init = (const unsigned char*)d_in[i];
    }
    if (!sv)   sv   = (const float*)d_in[0];
    if (!W)    W    = (const float*)d_in[1];
    if (!lab)  lab  = (const int*)d_in[2];
    if (!cent) cent = (const float*)d_in[3];
    if (!init) init = (const unsigned char*)d_in[4];

    float* out = (float*)d_out;

    accum_kernel<<<dim3(VBLOCKS, SPLIT), TPB>>>(sv, W, lab);
    finalize_kernel<<<(CC * VV / 4) / 256, 256>>>(cent, lab, init, out);
}

// round 8
// speedup vs baseline: 1.0247x; 1.0040x over previous
#include <cuda_runtime.h>
#include <cuda_bf16.h>

// Problem constants (fixed by the reference: B=512, V=32768, C=16)
#define BB   512
#define VV   32768
#define CC   16
#define TPB  256
#define SPLIT 8
#define BPS  (BB / SPLIT)      // 64 samples per split
#define VBLOCKS (VV / TPB)     // 128 v-tiles

// Deterministic scratch: per-split partial sums [SPLIT][C][V] (16 MB).
__device__ float g_partial[(size_t)SPLIT * CC * VV];

// ---------------------------------------------------------------------------
// Kernel 1: gather + |sv*w| + segment-sum into per-split partials.
// Grid (VBLOCKS, SPLIT); each thread owns one v column for 64 b's,
// accumulating in smem[class][tid] (same class across warp -> broadcast LDS
// + conflict-free STS). Measured DRAM-bound at 87% of peak against a
// ~1.15 GB mandatory-traffic floor (W_eff gather = 1 float per 64B burst).
// DO NOT PERTURB without re-deriving the traffic model.
// ---------------------------------------------------------------------------
__global__ __launch_bounds__(TPB) void accum_kernel(
    const float* __restrict__ sv,
    const float* __restrict__ W,
    const int*   __restrict__ labels)
{
    __shared__ float acc[CC][TPB];
    __shared__ int   slab[BPS];

    const int tid   = threadIdx.x;
    const int v     = blockIdx.x * TPB + tid;
    const int split = blockIdx.y;
    const int b0    = split * BPS;

    if (tid < BPS) slab[tid] = labels[b0 + tid];
#pragma unroll
    for (int c = 0; c < CC; ++c) acc[c][tid] = 0.0f;
    __syncthreads();

    const float* svp = sv + (size_t)b0 * VV + v;
    const float* Wp  = W  + ((size_t)b0 * VV + v) * CC;

    // 8 b's per batch: 16 independent global loads in flight per thread.
#pragma unroll 1
    for (int bb = 0; bb < BPS; bb += 8) {
        int   l[8];
        float s[8];
        float w[8];
#pragma unroll
        for (int k = 0; k < 8; ++k) l[k] = slab[bb + k];
#pragma unroll
        for (int k = 0; k < 8; ++k)
            s[k] = __ldcs(svp + (size_t)(bb + k) * VV);
#pragma unroll
        for (int k = 0; k < 8; ++k)
            w[k] = __ldcs(Wp + (size_t)(bb + k) * VV * CC + l[k]);
#pragma unroll
        for (int k = 0; k < 8; ++k)
            acc[l[k]][tid] += fabsf(s[k] * w[k]);
    }

    // Coalesced partial write (fully written -> no zeroing needed).
    // Default store policy keeps these L2-resident for the finalize pass.
    float* outp = g_partial + ((size_t)split * CC) * VV + v;
#pragma unroll
    for (int c = 0; c < CC; ++c)
        outp[(size_t)c * VV] = acc[c][tid];
}

// ---------------------------------------------------------------------------
// Kernel 2: fused count + init-decode + split-reduce + mean + EMA.
// float2 granularity: 262144 threads / 1024 blocks -> ~86% occupancy so the
// 8 independent partial loads per thread keep enough sectors in flight
// (R4 profile showed the float4/512-block version latency-bound at occ 37%).
// Each block's 512 contiguous outputs lie in exactly one class c.
// ---------------------------------------------------------------------------
__global__ __launch_bounds__(256) void finalize_kernel(
    const float*         __restrict__ centroids,
    const int*           __restrict__ labels,
    const unsigned char* __restrict__ initp,
    float*               __restrict__ out)
{
    const int idx2 = blockIdx.x * blockDim.x + threadIdx.x;   // over C*V/2
    const int idx  = idx2 * 2;
    const int c    = idx >> 15;          // /V  (constant within a block)
    const int v    = idx & (VV - 1);

    __shared__ int s_cnt;
    __shared__ int s_ini;
    if (threadIdx.x == 0) s_cnt = 0;
    __syncthreads();

    // Per-block count of labels == c (2 loads per thread, fully parallel).
    int my = 0;
#pragma unroll
    for (int b = threadIdx.x; b < BB; b += 256)
        my += (labels[b] == c);
    if (my) atomicAdd(&s_cnt, my);

    // Thread 0: decode initialized[c] with dtype sniff (vector loads).
    if (threadIdx.x == 0) {
        const int4  i4 = *(const int4*)initp;          // first 16 bytes
        const unsigned char* bp = (const unsigned char*)&i4;
        bool i32like = true, f32like = true, anyNZ = false;
        for (int i = 0; i < 16; ++i) {
            if ((i & 3) != 0 && bp[i] != 0) i32like = false;
            if (bp[i] != 0) anyNZ = true;
        }
        const float* fp = (const float*)&i4;
        for (int k = 0; k < 4; ++k)
            if (!(fp[k] == 0.0f || fp[k] == 1.0f)) f32like = false;

        int ini;
        if (!anyNZ)       ini = 0;                         // all-zero: representations agree
        else if (f32like) ini = (((const float*)initp)[c] != 0.0f);
        else if (i32like) ini = (((const int*)initp)[c] != 0);
        else              ini = (initp[c] != 0);
        s_ini = ini;
    }
    __syncthreads();

    const int cnt = s_cnt;
    const int ini = s_ini;

    // Deterministic split reduction (fixed order p = 0..7),
    // 8 independent float2 loads issued back-to-back for MLP.
    float2 t[SPLIT];
#pragma unroll
    for (int p = 0; p < SPLIT; ++p)
        t[p] = *(const float2*)&g_partial[((size_t)p * CC + c) * VV + v];

    float2 s = make_float2(0.f, 0.f);
#pragma unroll
    for (int p = 0; p < SPLIT; ++p) { s.x += t[p].x; s.y += t[p].y; }

    const float inv   = 1.0f / fmaxf((float)cnt, 1.0f);
    const float ALPHA = (float)(2.0 / 1001.0);  // 1 - MOMENTUM

    const float2 ct = *(const float2*)&centroids[idx];
    float2 r;
    {
        float m, u;
        m = s.x * inv; u = ini ? (ct.x + ALPHA * (m - ct.x)) : m; r.x = cnt > 0 ? u : ct.x;
        m = s.y * inv; u = ini ? (ct.y + ALPHA * (m - ct.y)) : m; r.y = cnt > 0 ? u : ct.y;
    }
    *(float2*)&out[idx] = r;
}

// ---------------------------------------------------------------------------
// Launch. Inputs bound by UNIQUE element count (robust to metadata order):
//   sparse_vector f32 [B,V]     -> 16,777,216
//   W_eff         f32 [B,V,C]   -> 268,435,456
//   labels        i32 [B]       -> 512
//   centroids     f32 [C,V]     -> 524,288
//   initialized   bool[C]       -> 16
// ---------------------------------------------------------------------------
extern "C" void kernel_launch(void* const* d_in, const int* in_sizes, int n_in,
                              void* d_out, int out_size)
{
    const float*         sv   = nullptr;
    const float*         W    = nullptr;
    const int*           lab  = nullptr;
    const float*         cent = nullptr;
    const unsigned char* init = nullptr;

    for (int i = 0; i < n_in; ++i) {
        long n = (long)in_sizes[i];
        if      (n == (long)BB * VV)       sv   = (const float*)d_in[i];
        else if (n == (long)BB * VV * CC)  W    = (const float*)d_in[i];
        else if (n == (long)BB)            lab  = (const int*)d_in[i];
        else if (n == (long)CC * VV)       cent = (const float*)d_in[i];
        else if (n == (long)CC)            init = (const unsigned char*)d_in[i];
    }
    if (!sv)   sv   = (const float*)d_in[0];
    if (!W)    W    = (const float*)d_in[1];
    if (!lab)  lab  = (const int*)d_in[2];
    if (!cent) cent = (const float*)d_in[3];
    if (!init) init = (const unsigned char*)d_in[4];

    float* out = (float*)d_out;

    accum_kernel<<<dim3(VBLOCKS, SPLIT), TPB>>>(sv, W, lab);
    finalize_kernel<<<(CC * VV / 2) / 256, 256>>>(cent, lab, init, out);
}